// round 4
// baseline (speedup 1.0000x reference)
#include <cuda_runtime.h>

#define ALPHA 0.2f

// Problem constants (fixed by the dataset)
#define B_   8
#define N_   1024
#define CIN  256
#define COUT 256
#define R_   4
#define H_   4
#define Cc   64   // channels per head

// Scratch (static device arrays; no runtime allocation)
__device__ __align__(16) float g_F [R_ * B_ * N_ * COUT];  // 32 MB
__device__ __align__(16) float g_li[R_ * B_ * N_ * H_];
__device__ __align__(16) float g_lj[R_ * B_ * N_ * H_];

// ---------------------------------------------------------------------------
// Kernel 1: F[r,b] = X[b] @ W[r]   (64x64 tile, 4x4 per thread, BK=32)
// grid (N/64, COUT/64, R*B), block 256
// ---------------------------------------------------------------------------
__global__ void gemm_kernel(const float* __restrict__ X,
                            const float* __restrict__ W)
{
    const int rb = blockIdx.z;
    const int r = rb >> 3, b = rb & 7;
    const float* A  = X + (size_t)b * N_ * CIN;
    const float* Bw = W + (size_t)r * CIN * COUT;
    float* out = g_F + (size_t)rb * N_ * COUT;

    __shared__ float As[32 * 68];  // [k][m], padded
    __shared__ float Bs[32 * 68];  // [k][n], padded

    const int tid = threadIdx.x;
    const int tx = tid & 15, ty = tid >> 4;
    const int m0 = blockIdx.x * 64, n0 = blockIdx.y * 64;

    float acc[4][4];
#pragma unroll
    for (int i = 0; i < 4; i++)
#pragma unroll
        for (int j = 0; j < 4; j++) acc[i][j] = 0.f;

    for (int k0 = 0; k0 < CIN; k0 += 32) {
#pragma unroll
        for (int l = 0; l < 8; l++) {
            int idx = l * 256 + tid;
            int m = idx >> 5, k = idx & 31;
            As[k * 68 + m] = A[(size_t)(m0 + m) * CIN + k0 + k];
            int kb = idx >> 6, n = idx & 63;
            Bs[kb * 68 + n] = Bw[(size_t)(k0 + kb) * COUT + n0 + n];
        }
        __syncthreads();
#pragma unroll
        for (int k = 0; k < 32; k++) {
            float av[4], bv[4];
#pragma unroll
            for (int i = 0; i < 4; i++) av[i] = As[k * 68 + ty * 4 + i];
#pragma unroll
            for (int j = 0; j < 4; j++) bv[j] = Bs[k * 68 + tx * 4 + j];
#pragma unroll
            for (int i = 0; i < 4; i++)
#pragma unroll
                for (int j = 0; j < 4; j++) acc[i][j] += av[i] * bv[j];
        }
        __syncthreads();
    }
#pragma unroll
    for (int i = 0; i < 4; i++)
#pragma unroll
        for (int j = 0; j < 4; j++)
            out[(size_t)(m0 + ty * 4 + i) * COUT + n0 + tx * 4 + j] = acc[i][j];
}

// ---------------------------------------------------------------------------
// Kernel 2: li/lj projections.  One thread per (r,b,n,h).
// ---------------------------------------------------------------------------
__global__ void lilj_kernel(const float* __restrict__ a)
{
    const int idx = blockIdx.x * blockDim.x + threadIdx.x;  // < R*B*N*H
    const int h  = idx & 3;
    const int n  = (idx >> 2) & (N_ - 1);
    const int rb = idx >> 12;
    const int r  = rb >> 3;

    const float4* f4  = (const float4*)(g_F + ((size_t)rb * N_ + n) * COUT + h * Cc);
    const float4* al4 = (const float4*)(a + (size_t)(r * H_ + h) * 2 * Cc);
    const float4* ar4 = al4 + (Cc / 4);

    float s1 = 0.f, s2 = 0.f;
#pragma unroll
    for (int c = 0; c < Cc / 4; c++) {
        float4 fv = f4[c], av = al4[c], rv = ar4[c];
        s1 += fv.x * av.x + fv.y * av.y + fv.z * av.z + fv.w * av.w;
        s2 += fv.x * rv.x + fv.y * rv.y + fv.z * rv.z + fv.w * rv.w;
    }
    g_li[idx] = s1;
    g_lj[idx] = s2;
}

// ---------------------------------------------------------------------------
// Kernel 3: attention + aggregation.
// One block per 32-row i-tile of one batch b.  256 threads.
// Single-pass unnormalized softmax: acc = sum_j e_j * F_j ; esum = sum_j e_j.
// adj read ONCE per block (all 4 relations packed to shared bitmasks).
// Warp w -> rows {w, w+8, w+16, w+24}; lane -> 8 output channels (h = lane>>3).
// ---------------------------------------------------------------------------
__global__ void attn_kernel(const int* __restrict__ adj,
                            float* __restrict__ out)
{
    extern __shared__ float smem[];
    float* Fs  = smem;                  // 64*256 floats  (F chunk)
    float* ljs = Fs + 64 * 256;         // 1024*4 floats  (lj for this r,b)
    float* lis = ljs + N_ * H_;         // 32*4 floats
    unsigned int* bits = (unsigned int*)(lis + 32 * H_);  // [r][il][jw] 4*32*32

    const int tid = threadIdx.x;
    const int blk = blockIdx.x;
    const int b  = blk >> 5;
    const int i0 = (blk & 31) * 32;

    // ---- pack adjacency bits for all 4 relations (adj last dim is R) ----
    const int4* adj4 = (const int4*)adj;
    for (int t = tid; t < 32 * 32; t += 256) {
        const int il = t >> 5;      // local row
        const int jw = t & 31;      // 32-bit word index over j
        const int4* ap = adj4 + ((size_t)(b * N_ + i0 + il) * N_ + jw * 32);
        unsigned int w0 = 0, w1 = 0, w2 = 0, w3 = 0;
#pragma unroll 8
        for (int jj = 0; jj < 32; jj++) {
            int4 v = ap[jj];
            w0 |= (unsigned int)(v.x != 0) << jj;
            w1 |= (unsigned int)(v.y != 0) << jj;
            w2 |= (unsigned int)(v.z != 0) << jj;
            w3 |= (unsigned int)(v.w != 0) << jj;
        }
        bits[(0 * 32 + il) * 32 + jw] = w0;
        bits[(1 * 32 + il) * 32 + jw] = w1;
        bits[(2 * 32 + il) * 32 + jw] = w2;
        bits[(3 * 32 + il) * 32 + jw] = w3;
    }

    const int warp = tid >> 5, lane = tid & 31;
    const int h = lane >> 3;

    float outacc[4][8];
#pragma unroll
    for (int t = 0; t < 4; t++)
#pragma unroll
        for (int k = 0; k < 8; k++) outacc[t][k] = 0.f;

    for (int r = 0; r < R_; r++) {
        __syncthreads();  // prev iteration consumers done (and bits ready on r=0)
        // stage lj / li for this (r,b)
        {
            const float4* ljg = (const float4*)(g_lj + (size_t)(r * B_ + b) * N_ * H_);
            float4* ljs4 = (float4*)ljs;
            for (int k = tid; k < N_; k += 256) ljs4[k] = ljg[k];
            if (tid < 32)
                ((float4*)lis)[tid] =
                    ((const float4*)(g_li + ((size_t)(r * B_ + b) * N_ + i0) * H_))[tid];
        }
        __syncthreads();

        float liv[4];
#pragma unroll
        for (int t = 0; t < 4; t++) liv[t] = lis[(warp + t * 8) * H_ + h];

        float racc[4][8];
        float esum[4];
#pragma unroll
        for (int t = 0; t < 4; t++) {
            esum[t] = 0.f;
#pragma unroll
            for (int k = 0; k < 8; k++) racc[t][k] = 0.f;
        }
        const unsigned int* bitsr = bits + r * 1024;
        const float* Fb = g_F + (size_t)(r * B_ + b) * N_ * COUT;

        for (int jc = 0; jc < 16; jc++) {           // 16 chunks of 64 j's
            __syncthreads();                         // prev chunk fully consumed
            const float4* Fg = (const float4*)(Fb + (size_t)(jc * 64) * COUT);
            float4* Fs4 = (float4*)Fs;
#pragma unroll
            for (int k = 0; k < 16; k++) Fs4[k * 256 + tid] = Fg[k * 256 + tid];
            __syncthreads();

#pragma unroll
            for (int jw = 0; jw < 2; jw++) {
                const int jwg = jc * 2 + jw;
                unsigned int wb[4];
#pragma unroll
                for (int t = 0; t < 4; t++) wb[t] = bitsr[(warp + t * 8) * 32 + jwg];
#pragma unroll 4
                for (int jj = 0; jj < 32; jj++) {
                    const int jl = jw * 32 + jj;
                    const float ljv = ljs[(jc * 64 + jl) * H_ + h];
                    const float4 fa = ((const float4*)Fs)[jl * 64 + lane * 2];
                    const float4 fb = ((const float4*)Fs)[jl * 64 + lane * 2 + 1];
#pragma unroll
                    for (int t = 0; t < 4; t++) {
                        float s = liv[t] + ljv;
                        s = fmaxf(s, ALPHA * s);     // leaky_relu (alpha<1)
                        float e = ((wb[t] >> jj) & 1u) ? __expf(s) : 0.f;
                        esum[t] += e;
                        racc[t][0] += e * fa.x; racc[t][1] += e * fa.y;
                        racc[t][2] += e * fa.z; racc[t][3] += e * fa.w;
                        racc[t][4] += e * fb.x; racc[t][5] += e * fb.y;
                        racc[t][6] += e * fb.z; racc[t][7] += e * fb.w;
                    }
                }
            }
        }

        // finalize this relation
#pragma unroll
        for (int t = 0; t < 4; t++) {
            const float es = esum[t];
            if (es > 0.f) {
                const float inv = 1.0f / es;
#pragma unroll
                for (int k = 0; k < 8; k++) outacc[t][k] += racc[t][k] * inv;
            } else {
                // fully-masked row: reference softmax degrades to uniform 1/N
                const float* Fp = Fb + lane * 8;
                float sacc[8];
#pragma unroll
                for (int k = 0; k < 8; k++) sacc[k] = 0.f;
                for (int j = 0; j < N_; j++) {
#pragma unroll
                    for (int k = 0; k < 8; k++) sacc[k] += Fp[(size_t)j * COUT + k];
                }
#pragma unroll
                for (int k = 0; k < 8; k++)
                    outacc[t][k] += sacc[k] * (1.0f / (float)N_);
            }
        }
    }

    // write output: out[b, i, h*64+c]
#pragma unroll
    for (int t = 0; t < 4; t++) {
        float* op = out + ((size_t)b * N_ + i0 + warp + t * 8) * COUT + lane * 8;
        float4 o0 = make_float4(outacc[t][0], outacc[t][1], outacc[t][2], outacc[t][3]);
        float4 o1 = make_float4(outacc[t][4], outacc[t][5], outacc[t][6], outacc[t][7]);
        ((float4*)op)[0] = o0;
        ((float4*)op)[1] = o1;
    }
}

// ---------------------------------------------------------------------------
extern "C" void kernel_launch(void* const* d_in, const int* in_sizes, int n_in,
                              void* d_out, int out_size)
{
    const float* X   = (const float*)d_in[0];   // node_feats (B,N,CIN)
    const int*   adj = (const int*)  d_in[1];   // adj (B,N,N,R)
    const float* W   = (const float*)d_in[2];   // (R,CIN,COUT)
    const float* a   = (const float*)d_in[3];   // (R,H,2C)
    float* out = (float*)d_out;                 // (B,N,H*C)

    dim3 gg(N_ / 64, COUT / 64, R_ * B_);
    gemm_kernel<<<gg, 256>>>(X, W);

    lilj_kernel<<<(R_ * B_ * N_ * H_) / 256, 256>>>(a);

    const int SMEM = (64 * 256 + N_ * H_ + 32 * H_) * 4 + R_ * 32 * 32 * 4;  // ~96.5 KB
    cudaFuncSetAttribute(attn_kernel, cudaFuncAttributeMaxDynamicSharedMemorySize, SMEM);
    attn_kernel<<<B_ * N_ / 32, 256, SMEM>>>(adj, out);
}

// round 5
// speedup vs baseline: 2.8835x; 2.8835x over previous
#include <cuda_runtime.h>

#define ALPHA 0.2f

// Problem constants (fixed by the dataset)
#define B_   8
#define N_   1024
#define CIN  256
#define COUT 256
#define R_   4
#define H_   4

// Scratch (static device arrays; no runtime allocation)
__device__ __align__(16) float  g_F  [R_ * B_ * N_ * COUT];   // 32 MB, fp32 (unrounded)
__device__ __align__(16) float2 g_eli[R_ * B_ * N_ * H_];     // (exp(li), exp(a*li))
__device__ __align__(16) float2 g_elj[R_ * B_ * N_ * H_];     // (exp(lj), exp(a*lj))

// ---------------------------------------------------------------------------
// Kernel 1: F[r,b] = X[b] @ W[r]   (64x64 tile, 4x4 per thread, BK=32)
// ---------------------------------------------------------------------------
__global__ void gemm_kernel(const float* __restrict__ X,
                            const float* __restrict__ W)
{
    const int rb = blockIdx.z;
    const int r = rb >> 3, b = rb & 7;
    const float* A  = X + (size_t)b * N_ * CIN;
    const float* Bw = W + (size_t)r * CIN * COUT;
    float* out = g_F + (size_t)rb * N_ * COUT;

    __shared__ float As[32 * 68];
    __shared__ float Bs[32 * 68];

    const int tid = threadIdx.x;
    const int tx = tid & 15, ty = tid >> 4;
    const int m0 = blockIdx.x * 64, n0 = blockIdx.y * 64;

    float acc[4][4];
#pragma unroll
    for (int i = 0; i < 4; i++)
#pragma unroll
        for (int j = 0; j < 4; j++) acc[i][j] = 0.f;

    for (int k0 = 0; k0 < CIN; k0 += 32) {
#pragma unroll
        for (int l = 0; l < 8; l++) {
            int idx = l * 256 + tid;
            int m = idx >> 5, k = idx & 31;
            As[k * 68 + m] = A[(size_t)(m0 + m) * CIN + k0 + k];
            int kb = idx >> 6, n = idx & 63;
            Bs[kb * 68 + n] = Bw[(size_t)(k0 + kb) * COUT + n0 + n];
        }
        __syncthreads();
#pragma unroll
        for (int k = 0; k < 32; k++) {
            float av[4], bv[4];
#pragma unroll
            for (int i = 0; i < 4; i++) av[i] = As[k * 68 + ty * 4 + i];
#pragma unroll
            for (int j = 0; j < 4; j++) bv[j] = Bs[k * 68 + tx * 4 + j];
#pragma unroll
            for (int i = 0; i < 4; i++)
#pragma unroll
                for (int j = 0; j < 4; j++) acc[i][j] += av[i] * bv[j];
        }
        __syncthreads();
    }
#pragma unroll
    for (int i = 0; i < 4; i++)
#pragma unroll
        for (int j = 0; j < 4; j++)
            out[(size_t)(m0 + ty * 4 + i) * COUT + n0 + tx * 4 + j] = acc[i][j];
}

// ---------------------------------------------------------------------------
// Kernel 2: li/lj projections + exp factorization.  One thread per (r,b,n,h).
// Stores (exp(l), exp(ALPHA*l)) so the attention kernel needs NO transcendentals:
//   exp(leaky_relu(li+lj)) == max(exp(li)*exp(lj), exp(a*li)*exp(a*lj))
// ---------------------------------------------------------------------------
__global__ void lilj_kernel(const float* __restrict__ a)
{
    const int idx = blockIdx.x * blockDim.x + threadIdx.x;  // < R*B*N*H
    const int h  = idx & 3;
    const int n  = (idx >> 2) & (N_ - 1);
    const int rb = idx >> 12;
    const int r  = rb >> 3;

    const float4* f4  = (const float4*)(g_F + ((size_t)rb * N_ + n) * COUT + h * 64);
    const float4* al4 = (const float4*)(a + (size_t)(r * H_ + h) * 128);
    const float4* ar4 = al4 + 16;

    float s1 = 0.f, s2 = 0.f;
#pragma unroll
    for (int c = 0; c < 16; c++) {
        float4 fv = f4[c], av = al4[c], rv = ar4[c];
        s1 += fv.x * av.x + fv.y * av.y + fv.z * av.z + fv.w * av.w;
        s2 += fv.x * rv.x + fv.y * rv.y + fv.z * rv.z + fv.w * rv.w;
    }
    g_eli[idx] = make_float2(__expf(s1), __expf(ALPHA * s1));
    g_elj[idx] = make_float2(__expf(s2), __expf(ALPHA * s2));
}

// ---------------------------------------------------------------------------
// Kernel 3: attention + aggregation via mma.sync tf32 tensor cores.
// Block: 64 i-rows of one batch, 512 threads = 16 warps = (mi 0..3) x (h 0..3).
// Each warp: out rows [i0+16*mi, +16), head h (64 channels) as 8 m16n8 tiles.
// Single-pass unnormalized softmax; esum from the SAME tf32-rounded P values.
// ---------------------------------------------------------------------------
#define FSTR 264   // F smem row stride (floats): 264 % 32 == 8 -> conflict-free B loads

__device__ __forceinline__ unsigned cvt_tf32(float f) {
    unsigned u;
    asm("cvt.rna.tf32.f32 %0, %1;" : "=r"(u) : "f"(f));
    return u;
}

__device__ __forceinline__ void mma_tf32(float* c,
                                         unsigned a0, unsigned a1, unsigned a2, unsigned a3,
                                         unsigned b0, unsigned b1) {
    asm volatile("mma.sync.aligned.m16n8k8.row.col.f32.tf32.tf32.f32 "
                 "{%0,%1,%2,%3}, {%4,%5,%6,%7}, {%8,%9}, {%0,%1,%2,%3};"
                 : "+f"(c[0]), "+f"(c[1]), "+f"(c[2]), "+f"(c[3])
                 : "r"(a0), "r"(a1), "r"(a2), "r"(a3), "r"(b0), "r"(b1));
}

__global__ __launch_bounds__(512, 1)
void attn_kernel(const int* __restrict__ adj, float* __restrict__ out)
{
    extern __shared__ float smem[];
    float*    Fs   = smem;                                // 64 * FSTR floats (tf32-rounded F chunk)
    float2*   Elj  = (float2*)(Fs + 64 * FSTR);           // [1024][4] (exp(lj), exp(a*lj))
    unsigned* bits = (unsigned*)(Elj + N_ * H_);          // [r][64][32] adjacency bitmasks

    const int tid = threadIdx.x;
    const int b  = blockIdx.x >> 4;                       // 128 blocks = 8 b x 16 tiles
    const int i0 = (blockIdx.x & 15) * 64;

    // ---- pack adjacency bits for all 4 relations (adj last dim is R) ----
    const int4* adj4 = (const int4*)adj;
    for (int tt = tid; tt < 64 * 32; tt += 512) {
        const int il = tt >> 5, jw = tt & 31;
        const int4* ap = adj4 + ((size_t)(b * N_ + i0 + il) * N_ + jw * 32);
        unsigned w0 = 0, w1 = 0, w2 = 0, w3 = 0;
#pragma unroll 8
        for (int jj = 0; jj < 32; jj++) {
            int4 v = ap[jj];
            w0 |= (unsigned)(v.x != 0) << jj;
            w1 |= (unsigned)(v.y != 0) << jj;
            w2 |= (unsigned)(v.z != 0) << jj;
            w3 |= (unsigned)(v.w != 0) << jj;
        }
        bits[(0 * 64 + il) * 32 + jw] = w0;
        bits[(1 * 64 + il) * 32 + jw] = w1;
        bits[(2 * 64 + il) * 32 + jw] = w2;
        bits[(3 * 64 + il) * 32 + jw] = w3;
    }

    const int warp = tid >> 5, lane = tid & 31;
    const int h = warp & 3, mi = warp >> 2;
    const int g = lane >> 2, t = lane & 3;                // mma group / thread-in-group
    const int r0 = mi * 16 + g, r1 = r0 + 8;              // local output rows for this lane
    const int nb = h * 64;                                // channel base for this warp

    float outacc[8][4];
#pragma unroll
    for (int nt = 0; nt < 8; nt++)
#pragma unroll
        for (int k = 0; k < 4; k++) outacc[nt][k] = 0.f;

    for (int r = 0; r < R_; r++) {
        __syncthreads();   // previous relation's Elj consumers done (bits ready on r=0)
        {  // stage Elj for (r,b)
            const float4* src = (const float4*)(g_elj + (size_t)(r * B_ + b) * N_ * H_);
            float4* dst = (float4*)Elj;
#pragma unroll
            for (int k = 0; k < 4; k++) dst[k * 512 + tid] = src[k * 512 + tid];
        }
        __syncthreads();

        const float2 ei0 = g_eli[((size_t)(r * B_ + b) * N_ + i0 + r0) * H_ + h];
        const float2 ei1 = g_eli[((size_t)(r * B_ + b) * N_ + i0 + r1) * H_ + h];

        float racc[8][4];
#pragma unroll
        for (int nt = 0; nt < 8; nt++)
#pragma unroll
            for (int k = 0; k < 4; k++) racc[nt][k] = 0.f;
        float es0 = 0.f, es1 = 0.f;

        const float* Fb = g_F + (size_t)(r * B_ + b) * N_ * COUT;
        const unsigned* bw0p = bits + (r * 64 + r0) * 32;
        const unsigned* bw1p = bits + (r * 64 + r1) * 32;

        for (int jc = 0; jc < 16; jc++) {                 // 16 chunks of 64 j's
            __syncthreads();                              // prev chunk fully consumed
            {  // stage F chunk, rounded to tf32
                const float4* Fg = (const float4*)(Fb + (size_t)jc * 64 * COUT);
#pragma unroll
                for (int k = 0; k < 8; k++) {
                    int e = k * 512 + tid;                // < 4096 float4
                    int row = e >> 6, c4 = e & 63;
                    float4 v = Fg[e];
                    v.x = __uint_as_float(cvt_tf32(v.x));
                    v.y = __uint_as_float(cvt_tf32(v.y));
                    v.z = __uint_as_float(cvt_tf32(v.z));
                    v.w = __uint_as_float(cvt_tf32(v.w));
                    *(float4*)(Fs + row * FSTR + c4 * 4) = v;
                }
            }
            __syncthreads();

            const unsigned bw0[2] = { bw0p[jc * 2], bw0p[jc * 2 + 1] };
            const unsigned bw1[2] = { bw1p[jc * 2], bw1p[jc * 2 + 1] };

#pragma unroll
            for (int kc = 0; kc < 8; kc++) {              // 8 k-slabs of 8 j's
                const int jb = kc * 8;
                const unsigned wr0 = bw0[kc >> 2], wr1 = bw1[kc >> 2];
                const int sl = (jb & 31) + t;

                const float2 ejA = Elj[(jc * 64 + jb + t) * H_ + h];
                const float2 ejB = Elj[(jc * 64 + jb + t + 4) * H_ + h];

                // exp(leaky_relu(li+lj)) = max(e^li * e^lj, e^(a li) * e^(a lj))
                float e00 = fmaxf(ei0.x * ejA.x, ei0.y * ejA.y);
                float e10 = fmaxf(ei1.x * ejA.x, ei1.y * ejA.y);
                float e02 = fmaxf(ei0.x * ejB.x, ei0.y * ejB.y);
                float e12 = fmaxf(ei1.x * ejB.x, ei1.y * ejB.y);
                e00 = ((wr0 >> sl) & 1u)       ? e00 : 0.f;
                e10 = ((wr1 >> sl) & 1u)       ? e10 : 0.f;
                e02 = ((wr0 >> (sl + 4)) & 1u) ? e02 : 0.f;
                e12 = ((wr1 >> (sl + 4)) & 1u) ? e12 : 0.f;

                const unsigned a0 = cvt_tf32(e00), a1 = cvt_tf32(e10);
                const unsigned a2 = cvt_tf32(e02), a3 = cvt_tf32(e12);
                // esum from the SAME rounded values -> normalization consistent with MMA
                es0 += __uint_as_float(a0) + __uint_as_float(a2);
                es1 += __uint_as_float(a1) + __uint_as_float(a3);

                const float* brow0 = Fs + (jb + t) * FSTR + nb + g;
                const float* brow1 = brow0 + 4 * FSTR;
#pragma unroll
                for (int nt = 0; nt < 8; nt++) {
                    unsigned b0 = __float_as_uint(brow0[nt * 8]);
                    unsigned b1 = __float_as_uint(brow1[nt * 8]);
                    mma_tf32(racc[nt], a0, a1, a2, a3, b0, b1);
                }
            }
        }

        // full row sums: reduce across the 4 lanes of each group (same g)
        es0 += __shfl_xor_sync(0xffffffffu, es0, 1);
        es0 += __shfl_xor_sync(0xffffffffu, es0, 2);
        es1 += __shfl_xor_sync(0xffffffffu, es1, 1);
        es1 += __shfl_xor_sync(0xffffffffu, es1, 2);
        const float inv0 = es0 > 0.f ? 1.0f / es0 : 0.f;
        const float inv1 = es1 > 0.f ? 1.0f / es1 : 0.f;

#pragma unroll
        for (int nt = 0; nt < 8; nt++) {
            outacc[nt][0] += racc[nt][0] * inv0;
            outacc[nt][1] += racc[nt][1] * inv0;
            outacc[nt][2] += racc[nt][2] * inv1;
            outacc[nt][3] += racc[nt][3] * inv1;
        }
    }

    // store: out[b, i, h*64 + c]
    float* o0 = out + ((size_t)b * N_ + i0 + r0) * COUT + nb + 2 * t;
    float* o1 = out + ((size_t)b * N_ + i0 + r1) * COUT + nb + 2 * t;
#pragma unroll
    for (int nt = 0; nt < 8; nt++) {
        *(float2*)(o0 + nt * 8) = make_float2(outacc[nt][0], outacc[nt][1]);
        *(float2*)(o1 + nt * 8) = make_float2(outacc[nt][2], outacc[nt][3]);
    }
}

// ---------------------------------------------------------------------------
extern "C" void kernel_launch(void* const* d_in, const int* in_sizes, int n_in,
                              void* d_out, int out_size)
{
    const float* X   = (const float*)d_in[0];   // node_feats (B,N,CIN)
    const int*   adj = (const int*)  d_in[1];   // adj (B,N,N,R)
    const float* W   = (const float*)d_in[2];   // (R,CIN,COUT)
    const float* a   = (const float*)d_in[3];   // (R,H,2C)
    float* out = (float*)d_out;                 // (B,N,H*C)

    dim3 gg(N_ / 64, COUT / 64, R_ * B_);
    gemm_kernel<<<gg, 256>>>(X, W);

    lilj_kernel<<<(R_ * B_ * N_ * H_) / 256, 256>>>(a);

    const int SMEM = (64 * FSTR) * 4 + (N_ * H_) * 8 + (R_ * 64 * 32) * 4;  // 133,120 B
    cudaFuncSetAttribute(attn_kernel, cudaFuncAttributeMaxDynamicSharedMemorySize, SMEM);
    attn_kernel<<<(B_ * N_) / 64, 512, SMEM>>>(adj, out);
}

// round 8
// speedup vs baseline: 4.2584x; 1.4768x over previous
#include <cuda_runtime.h>
#include <cstdint>

#define ALPHA 0.2f

// Problem constants (fixed by the dataset)
#define B_   8
#define N_   1024
#define CIN  256
#define COUT 256
#define R_   4
#define H_   4

// Scratch (static device arrays; no runtime allocation)
__device__ __align__(16) float  g_F  [R_ * B_ * N_ * COUT];   // 32 MB, tf32-rounded fp32
__device__ __align__(16) float2 g_eli[R_ * B_ * N_ * H_];     // (exp(li), exp(a*li))
__device__ __align__(16) float2 g_elj[R_ * B_ * N_ * H_];     // (exp(lj), exp(a*lj))

// ---------------------------------------------------------------------------
// helpers
// ---------------------------------------------------------------------------
__device__ __forceinline__ unsigned cvt_tf32(float f) {
    unsigned u;
    asm("cvt.rna.tf32.f32 %0, %1;" : "=r"(u) : "f"(f));
    return u;
}

__device__ __forceinline__ void mma_tf32(float* c,
                                         unsigned a0, unsigned a1, unsigned a2, unsigned a3,
                                         unsigned b0, unsigned b1) {
    asm volatile("mma.sync.aligned.m16n8k8.row.col.f32.tf32.tf32.f32 "
                 "{%0,%1,%2,%3}, {%4,%5,%6,%7}, {%8,%9}, {%0,%1,%2,%3};"
                 : "+f"(c[0]), "+f"(c[1]), "+f"(c[2]), "+f"(c[3])
                 : "r"(a0), "r"(a1), "r"(a2), "r"(a3), "r"(b0), "r"(b1));
}

__device__ __forceinline__ void cpa16(uint32_t dst, const void* src) {
    asm volatile("cp.async.cg.shared.global [%0], [%1], 16;" :: "r"(dst), "l"(src));
}
#define CP_COMMIT() asm volatile("cp.async.commit_group;")
#define CP_WAIT(n)  asm volatile("cp.async.wait_group %0;" :: "n"(n))

// ---------------------------------------------------------------------------
// Kernel 1: F[r,b] = X[b] @ W[r] via tf32 mma.sync.
// Block tile 128x128 (256 thr = 8 warps, warp tile 32x64), K staged 16 at a
// time with cp.async double buffering.  Epilogue stores F rounded to tf32.
// ---------------------------------------------------------------------------
#define PADK 20
#define PADN 136

__global__ __launch_bounds__(256, 2)
void gemm_kernel(const float* __restrict__ X, const float* __restrict__ W)
{
    const int rb = blockIdx.z, r = rb >> 3, b = rb & 7;
    const float* Ag = X + (size_t)b * N_ * CIN;
    const float* Bg = W + (size_t)r * CIN * COUT;
    float* out = g_F + (size_t)rb * N_ * COUT;
    const int m0 = blockIdx.x * 128, n0 = blockIdx.y * 128;

    __shared__ float As[2][128 * PADK];
    __shared__ float Bs[2][16 * PADN];

    const int tid = threadIdx.x, warp = tid >> 5, lane = tid & 31;
    const int wm = (warp & 3) * 32, wn = (warp >> 2) * 64;
    const int g = lane >> 2, t = lane & 3;

    const uint32_t sA = (uint32_t)__cvta_generic_to_shared(&As[0][0]);
    const uint32_t sB = (uint32_t)__cvta_generic_to_shared(&Bs[0][0]);

    float acc[2][8][4];
#pragma unroll
    for (int mt = 0; mt < 2; mt++)
#pragma unroll
        for (int nt = 0; nt < 8; nt++)
#pragma unroll
            for (int k = 0; k < 4; k++) acc[mt][nt][k] = 0.f;

    auto stage = [&](int s) {
        const int buf = s & 1, k0 = s * 16;
#pragma unroll
        for (int i = 0; i < 2; i++) {                 // A: 512 float4
            int idx = tid * 2 + i;
            int row = idx >> 2, c = idx & 3;
            cpa16(sA + (uint32_t)(buf * (128 * PADK) + row * PADK + c * 4) * 4,
                  Ag + (size_t)(m0 + row) * CIN + k0 + c * 4);
        }
#pragma unroll
        for (int i = 0; i < 2; i++) {                 // B: 512 float4
            int idx = tid * 2 + i;
            int row = idx >> 5, c = idx & 31;
            cpa16(sB + (uint32_t)(buf * (16 * PADN) + row * PADN + c * 4) * 4,
                  Bg + (size_t)(k0 + row) * COUT + n0 + c * 4);
        }
        CP_COMMIT();
    };

    stage(0);
    for (int s = 0; s < 16; s++) {
        if (s + 1 < 16) { stage(s + 1); CP_WAIT(1); } else { CP_WAIT(0); }
        __syncthreads();
        const float* Ab = As[s & 1];
        const float* Bb = Bs[s & 1];
#pragma unroll
        for (int kk = 0; kk < 16; kk += 8) {
            unsigned af[2][4], bf[8][2];
#pragma unroll
            for (int mt = 0; mt < 2; mt++) {
                int rowb = wm + mt * 16 + g;
                af[mt][0] = cvt_tf32(Ab[rowb * PADK + kk + t]);
                af[mt][1] = cvt_tf32(Ab[(rowb + 8) * PADK + kk + t]);
                af[mt][2] = cvt_tf32(Ab[rowb * PADK + kk + 4 + t]);
                af[mt][3] = cvt_tf32(Ab[(rowb + 8) * PADK + kk + 4 + t]);
            }
#pragma unroll
            for (int nt = 0; nt < 8; nt++) {
                int col = wn + nt * 8 + g;
                bf[nt][0] = cvt_tf32(Bb[(kk + t) * PADN + col]);
                bf[nt][1] = cvt_tf32(Bb[(kk + 4 + t) * PADN + col]);
            }
#pragma unroll
            for (int mt = 0; mt < 2; mt++)
#pragma unroll
                for (int nt = 0; nt < 8; nt++)
                    mma_tf32(acc[mt][nt], af[mt][0], af[mt][1], af[mt][2], af[mt][3],
                             bf[nt][0], bf[nt][1]);
        }
        __syncthreads();
    }

    // epilogue: store F pre-rounded to tf32 (rna) so attn can cp.async it raw
#pragma unroll
    for (int mt = 0; mt < 2; mt++) {
        int row = m0 + wm + mt * 16 + g;
#pragma unroll
        for (int nt = 0; nt < 8; nt++) {
            int col = n0 + wn + nt * 8 + 2 * t;
            float2 v0 = make_float2(__uint_as_float(cvt_tf32(acc[mt][nt][0])),
                                    __uint_as_float(cvt_tf32(acc[mt][nt][1])));
            float2 v1 = make_float2(__uint_as_float(cvt_tf32(acc[mt][nt][2])),
                                    __uint_as_float(cvt_tf32(acc[mt][nt][3])));
            *(float2*)(out + (size_t)row * COUT + col) = v0;
            *(float2*)(out + (size_t)(row + 8) * COUT + col) = v1;
        }
    }
}

// ---------------------------------------------------------------------------
// Kernel 2: li/lj projections + exp factorization.  One thread per (r,b,n,h).
//   exp(leaky_relu(li+lj)) == max(exp(li)*exp(lj), exp(a*li)*exp(a*lj))
// ---------------------------------------------------------------------------
__global__ void lilj_kernel(const float* __restrict__ a)
{
    const int idx = blockIdx.x * blockDim.x + threadIdx.x;  // < R*B*N*H
    const int h  = idx & 3;
    const int n  = (idx >> 2) & (N_ - 1);
    const int rb = idx >> 12;
    const int r  = rb >> 3;

    const float4* f4  = (const float4*)(g_F + ((size_t)rb * N_ + n) * COUT + h * 64);
    const float4* al4 = (const float4*)(a + (size_t)(r * H_ + h) * 128);
    const float4* ar4 = al4 + 16;

    float s1 = 0.f, s2 = 0.f;
#pragma unroll
    for (int c = 0; c < 16; c++) {
        float4 fv = f4[c], av = al4[c], rv = ar4[c];
        s1 += fv.x * av.x + fv.y * av.y + fv.z * av.z + fv.w * av.w;
        s2 += fv.x * rv.x + fv.y * rv.y + fv.z * rv.z + fv.w * rv.w;
    }
    g_eli[idx] = make_float2(__expf(s1), __expf(ALPHA * s1));
    g_elj[idx] = make_float2(__expf(s2), __expf(ALPHA * s2));
}

// ---------------------------------------------------------------------------
// Kernel 3: attention + aggregation via mma.sync tf32, cp.async double-buffered
// F staging (F already tf32-rounded in gmem -> staging is a raw async copy).
// Block: 64 i-rows of one batch, 512 threads = 16 warps = (mi 0..3) x (h 0..3).
// ---------------------------------------------------------------------------
#define FSTR 264            // F smem row stride (floats)
#define FBUF (64 * FSTR)    // floats per buffer

__global__ __launch_bounds__(512, 1)
void attn_kernel(const int* __restrict__ adj, float* __restrict__ out)
{
    extern __shared__ float smem[];
    float*    Fs   = smem;                                // 2 buffers of 64*FSTR
    float2*   Elj  = (float2*)(Fs + 2 * FBUF);            // [1024][4]
    unsigned* bits = (unsigned*)(Elj + N_ * H_);          // [r][64][32]

    const uint32_t sF = (uint32_t)__cvta_generic_to_shared(Fs);

    const int tid = threadIdx.x;
    const int b  = blockIdx.x >> 4;                       // 128 blocks = 8 b x 16 tiles
    const int i0 = (blockIdx.x & 15) * 64;

    // ---- pack adjacency bits for all 4 relations (adj last dim is R) ----
    const int4* adj4 = (const int4*)adj;
    for (int tt = tid; tt < 64 * 32; tt += 512) {
        const int il = tt >> 5, jw = tt & 31;
        const int4* ap = adj4 + ((size_t)(b * N_ + i0 + il) * N_ + jw * 32);
        unsigned w0 = 0, w1 = 0, w2 = 0, w3 = 0;
#pragma unroll 8
        for (int jj = 0; jj < 32; jj++) {
            int4 v = ap[jj];
            w0 |= (unsigned)(v.x != 0) << jj;
            w1 |= (unsigned)(v.y != 0) << jj;
            w2 |= (unsigned)(v.z != 0) << jj;
            w3 |= (unsigned)(v.w != 0) << jj;
        }
        bits[(0 * 64 + il) * 32 + jw] = w0;
        bits[(1 * 64 + il) * 32 + jw] = w1;
        bits[(2 * 64 + il) * 32 + jw] = w2;
        bits[(3 * 64 + il) * 32 + jw] = w3;
    }

    const int warp = tid >> 5, lane = tid & 31;
    const int h = warp & 3, mi = warp >> 2;
    const int g = lane >> 2, t = lane & 3;
    const int r0 = mi * 16 + g, r1 = r0 + 8;
    const int nb = h * 64;

    auto stageF = [&](const float* Fb, int jc) {
        const int buf = jc & 1;
        const float* src = Fb + (size_t)jc * 64 * COUT;
        const uint32_t dst = sF + (uint32_t)(buf * FBUF) * 4;
#pragma unroll
        for (int k = 0; k < 8; k++) {
            int e = k * 512 + tid;            // 0..4095 float4
            int row = e >> 6, c4 = e & 63;
            cpa16(dst + (uint32_t)(row * FSTR + c4 * 4) * 4, src + (size_t)e * 4);
        }
        CP_COMMIT();
    };

    float outacc[8][4];
#pragma unroll
    for (int nt = 0; nt < 8; nt++)
#pragma unroll
        for (int k = 0; k < 4; k++) outacc[nt][k] = 0.f;

    for (int r = 0; r < R_; r++) {
        // stage Elj for (r,b) (small, plain copy) + prologue-stage chunk 0
        {
            const float4* src = (const float4*)(g_elj + (size_t)(r * B_ + b) * N_ * H_);
            float4* dst = (float4*)Elj;
#pragma unroll
            for (int k = 0; k < 4; k++) dst[k * 512 + tid] = src[k * 512 + tid];
        }
        const float* Fb = g_F + (size_t)(r * B_ + b) * N_ * COUT;
        stageF(Fb, 0);

        const float2 ei0 = g_eli[((size_t)(r * B_ + b) * N_ + i0 + r0) * H_ + h];
        const float2 ei1 = g_eli[((size_t)(r * B_ + b) * N_ + i0 + r1) * H_ + h];

        float racc[8][4];
#pragma unroll
        for (int nt = 0; nt < 8; nt++)
#pragma unroll
            for (int k = 0; k < 4; k++) racc[nt][k] = 0.f;
        float es0 = 0.f, es1 = 0.f;

        const unsigned* bw0p = bits + (r * 64 + r0) * 32;
        const unsigned* bw1p = bits + (r * 64 + r1) * 32;

        for (int jc = 0; jc < 16; jc++) {
            if (jc + 1 < 16) { stageF(Fb, jc + 1); CP_WAIT(1); } else { CP_WAIT(0); }
            __syncthreads();                              // staged data (+Elj/bits) visible
            const float* Fsb = Fs + (jc & 1) * FBUF;

            const unsigned bw0[2] = { bw0p[jc * 2], bw0p[jc * 2 + 1] };
            const unsigned bw1[2] = { bw1p[jc * 2], bw1p[jc * 2 + 1] };

#pragma unroll
            for (int kc = 0; kc < 8; kc++) {              // 8 k-slabs of 8 j's
                const int jb = kc * 8;
                const unsigned wr0 = bw0[kc >> 2], wr1 = bw1[kc >> 2];
                const int sl = (jb & 31) + t;

                const float2 ejA = Elj[(jc * 64 + jb + t) * H_ + h];
                const float2 ejB = Elj[(jc * 64 + jb + t + 4) * H_ + h];

                // exp(leaky_relu(li+lj)) = max(e^li*e^lj, e^(a li)*e^(a lj))
                float e00 = fmaxf(ei0.x * ejA.x, ei0.y * ejA.y);
                float e10 = fmaxf(ei1.x * ejA.x, ei1.y * ejA.y);
                float e02 = fmaxf(ei0.x * ejB.x, ei0.y * ejB.y);
                float e12 = fmaxf(ei1.x * ejB.x, ei1.y * ejB.y);
                e00 = ((wr0 >> sl) & 1u)       ? e00 : 0.f;
                e10 = ((wr1 >> sl) & 1u)       ? e10 : 0.f;
                e02 = ((wr0 >> (sl + 4)) & 1u) ? e02 : 0.f;
                e12 = ((wr1 >> (sl + 4)) & 1u) ? e12 : 0.f;

                const unsigned a0 = cvt_tf32(e00), a1 = cvt_tf32(e10);
                const unsigned a2 = cvt_tf32(e02), a3 = cvt_tf32(e12);
                es0 += __uint_as_float(a0) + __uint_as_float(a2);
                es1 += __uint_as_float(a1) + __uint_as_float(a3);

                const float* brow0 = Fsb + (jb + t) * FSTR + nb + g;
                const float* brow1 = brow0 + 4 * FSTR;
#pragma unroll
                for (int nt = 0; nt < 8; nt++) {
                    unsigned b0 = __float_as_uint(brow0[nt * 8]);
                    unsigned b1 = __float_as_uint(brow1[nt * 8]);
                    mma_tf32(racc[nt], a0, a1, a2, a3, b0, b1);
                }
            }
            __syncthreads();                              // buffer free for restage
        }

        // row sums: reduce across the 4 lanes of each group
        es0 += __shfl_xor_sync(0xffffffffu, es0, 1);
        es0 += __shfl_xor_sync(0xffffffffu, es0, 2);
        es1 += __shfl_xor_sync(0xffffffffu, es1, 1);
        es1 += __shfl_xor_sync(0xffffffffu, es1, 2);
        const float inv0 = es0 > 0.f ? 1.0f / es0 : 0.f;
        const float inv1 = es1 > 0.f ? 1.0f / es1 : 0.f;

#pragma unroll
        for (int nt = 0; nt < 8; nt++) {
            outacc[nt][0] += racc[nt][0] * inv0;
            outacc[nt][1] += racc[nt][1] * inv0;
            outacc[nt][2] += racc[nt][2] * inv1;
            outacc[nt][3] += racc[nt][3] * inv1;
        }
        __syncthreads();                                  // Elj free for next r
    }

    // store: out[b, i, h*64 + c]
    float* o0 = out + ((size_t)b * N_ + i0 + r0) * COUT + nb + 2 * t;
    float* o1 = out + ((size_t)b * N_ + i0 + r1) * COUT + nb + 2 * t;
#pragma unroll
    for (int nt = 0; nt < 8; nt++) {
        *(float2*)(o0 + nt * 8) = make_float2(outacc[nt][0], outacc[nt][1]);
        *(float2*)(o1 + nt * 8) = make_float2(outacc[nt][2], outacc[nt][3]);
    }
}

// ---------------------------------------------------------------------------
extern "C" void kernel_launch(void* const* d_in, const int* in_sizes, int n_in,
                              void* d_out, int out_size)
{
    const float* X   = (const float*)d_in[0];   // node_feats (B,N,CIN)
    const int*   adj = (const int*)  d_in[1];   // adj (B,N,N,R)
    const float* W   = (const float*)d_in[2];   // (R,CIN,COUT)
    const float* a   = (const float*)d_in[3];   // (R,H,2C)
    float* out = (float*)d_out;                 // (B,N,H*C)

    gemm_kernel<<<dim3(N_ / 128, COUT / 128, R_ * B_), 256>>>(X, W);

    lilj_kernel<<<(R_ * B_ * N_ * H_) / 256, 256>>>(a);

    const int SMEM = (2 * FBUF) * 4 + (N_ * H_) * 8 + (R_ * 64 * 32) * 4;  // 200704 B
    cudaFuncSetAttribute(attn_kernel, cudaFuncAttributeMaxDynamicSharedMemorySize, SMEM);
    attn_kernel<<<(B_ * N_) / 64, 512, SMEM>>>(adj, out);
}

// round 10
// speedup vs baseline: 4.6728x; 1.0973x over previous
#include <cuda_runtime.h>
#include <cstdint>

#define ALPHA 0.2f

// Problem constants (fixed by the dataset)
#define B_   8
#define N_   1024
#define CIN  256
#define COUT 256
#define R_   4
#define H_   4

// Scratch (static device arrays; no runtime allocation)
__device__ __align__(16) float  g_F  [R_ * B_ * N_ * COUT];   // 32 MB, tf32-rounded fp32
__device__ __align__(16) float2 g_eli[R_ * B_ * N_ * H_];     // (exp(li), exp(a*li))
__device__ __align__(16) float2 g_elj[R_ * B_ * N_ * H_];     // (exp(lj), exp(a*lj))

// ---------------------------------------------------------------------------
// helpers
// ---------------------------------------------------------------------------
__device__ __forceinline__ unsigned cvt_tf32(float f) {
    unsigned u;
    asm("cvt.rna.tf32.f32 %0, %1;" : "=r"(u) : "f"(f));
    return u;
}

__device__ __forceinline__ void mma_tf32(float* c,
                                         unsigned a0, unsigned a1, unsigned a2, unsigned a3,
                                         unsigned b0, unsigned b1) {
    asm volatile("mma.sync.aligned.m16n8k8.row.col.f32.tf32.tf32.f32 "
                 "{%0,%1,%2,%3}, {%4,%5,%6,%7}, {%8,%9}, {%0,%1,%2,%3};"
                 : "+f"(c[0]), "+f"(c[1]), "+f"(c[2]), "+f"(c[3])
                 : "r"(a0), "r"(a1), "r"(a2), "r"(a3), "r"(b0), "r"(b1));
}

__device__ __forceinline__ void cpa16(uint32_t dst, const void* src) {
    asm volatile("cp.async.cg.shared.global [%0], [%1], 16;" :: "r"(dst), "l"(src));
}
#define CP_COMMIT() asm volatile("cp.async.commit_group;")
#define CP_WAIT(n)  asm volatile("cp.async.wait_group %0;" :: "n"(n))

// ---------------------------------------------------------------------------
// Kernel 1: F[r,b] = X[b] @ W[r] via tf32 mma.sync, with li/lj FUSED into the
// epilogue.  Block tile 128x128, warp tile 32x64 == (32 rows x 1 full head),
// so full 64-channel dots with a_l/a_r reduce within one warp.
// ---------------------------------------------------------------------------
#define PADK 20
#define PADN 136

__global__ __launch_bounds__(256, 2)
void gemm_kernel(const float* __restrict__ X, const float* __restrict__ W,
                 const float* __restrict__ a)
{
    const int rb = blockIdx.z, r = rb >> 3, b = rb & 7;
    const float* Ag = X + (size_t)b * N_ * CIN;
    const float* Bg = W + (size_t)r * CIN * COUT;
    float* out = g_F + (size_t)rb * N_ * COUT;
    const int m0 = blockIdx.x * 128, n0 = blockIdx.y * 128;

    __shared__ float As[2][128 * PADK];
    __shared__ float Bs[2][16 * PADN];

    const int tid = threadIdx.x, warp = tid >> 5, lane = tid & 31;
    const int wm = (warp & 3) * 32, wn = (warp >> 2) * 64;
    const int g = lane >> 2, t = lane & 3;

    const uint32_t sA = (uint32_t)__cvta_generic_to_shared(&As[0][0]);
    const uint32_t sB = (uint32_t)__cvta_generic_to_shared(&Bs[0][0]);

    float acc[2][8][4];
#pragma unroll
    for (int mt = 0; mt < 2; mt++)
#pragma unroll
        for (int nt = 0; nt < 8; nt++)
#pragma unroll
            for (int k = 0; k < 4; k++) acc[mt][nt][k] = 0.f;

    auto stage = [&](int s) {
        const int buf = s & 1, k0 = s * 16;
#pragma unroll
        for (int i = 0; i < 2; i++) {
            int idx = tid * 2 + i;
            int row = idx >> 2, c = idx & 3;
            cpa16(sA + (uint32_t)(buf * (128 * PADK) + row * PADK + c * 4) * 4,
                  Ag + (size_t)(m0 + row) * CIN + k0 + c * 4);
        }
#pragma unroll
        for (int i = 0; i < 2; i++) {
            int idx = tid * 2 + i;
            int row = idx >> 5, c = idx & 31;
            cpa16(sB + (uint32_t)(buf * (16 * PADN) + row * PADN + c * 4) * 4,
                  Bg + (size_t)(k0 + row) * COUT + n0 + c * 4);
        }
        CP_COMMIT();
    };

    stage(0);
    for (int s = 0; s < 16; s++) {
        if (s + 1 < 16) { stage(s + 1); CP_WAIT(1); } else { CP_WAIT(0); }
        __syncthreads();
        const float* Ab = As[s & 1];
        const float* Bb = Bs[s & 1];
#pragma unroll
        for (int kk = 0; kk < 16; kk += 8) {
            unsigned af[2][4], bf[8][2];
#pragma unroll
            for (int mt = 0; mt < 2; mt++) {
                int rowb = wm + mt * 16 + g;
                af[mt][0] = cvt_tf32(Ab[rowb * PADK + kk + t]);
                af[mt][1] = cvt_tf32(Ab[(rowb + 8) * PADK + kk + t]);
                af[mt][2] = cvt_tf32(Ab[rowb * PADK + kk + 4 + t]);
                af[mt][3] = cvt_tf32(Ab[(rowb + 8) * PADK + kk + 4 + t]);
            }
#pragma unroll
            for (int nt = 0; nt < 8; nt++) {
                int col = wn + nt * 8 + g;
                bf[nt][0] = cvt_tf32(Bb[(kk + t) * PADN + col]);
                bf[nt][1] = cvt_tf32(Bb[(kk + 4 + t) * PADN + col]);
            }
#pragma unroll
            for (int mt = 0; mt < 2; mt++)
#pragma unroll
                for (int nt = 0; nt < 8; nt++)
                    mma_tf32(acc[mt][nt], af[mt][0], af[mt][1], af[mt][2], af[mt][3],
                             bf[nt][0], bf[nt][1]);
        }
        __syncthreads();
    }

    // ---- fused li/lj epilogue: warp tile covers head h fully ----
    {
        const int h = blockIdx.y * 2 + (warp >> 2);
        const float2* al2 = (const float2*)(a + (size_t)(r * H_ + h) * 128);
        const float2* ar2 = al2 + 32;   // +64 floats
#pragma unroll
        for (int mt = 0; mt < 2; mt++) {
            float sliA = 0.f, sliB = 0.f, sljA = 0.f, sljB = 0.f;
#pragma unroll
            for (int nt = 0; nt < 8; nt++) {
                float2 al = al2[nt * 4 + t];
                float2 ar = ar2[nt * 4 + t];
                sliA += acc[mt][nt][0] * al.x + acc[mt][nt][1] * al.y;
                sliB += acc[mt][nt][2] * al.x + acc[mt][nt][3] * al.y;
                sljA += acc[mt][nt][0] * ar.x + acc[mt][nt][1] * ar.y;
                sljB += acc[mt][nt][2] * ar.x + acc[mt][nt][3] * ar.y;
            }
#pragma unroll
            for (int d = 1; d < 4; d <<= 1) {
                sliA += __shfl_xor_sync(0xffffffffu, sliA, d);
                sliB += __shfl_xor_sync(0xffffffffu, sliB, d);
                sljA += __shfl_xor_sync(0xffffffffu, sljA, d);
                sljB += __shfl_xor_sync(0xffffffffu, sljB, d);
            }
            if (t == 0) {
                const int row = m0 + wm + mt * 16 + g;
                const size_t base = ((size_t)(r * B_ + b) * N_ + row) * H_ + h;
                g_eli[base] = make_float2(__expf(sliA), __expf(ALPHA * sliA));
                g_elj[base] = make_float2(__expf(sljA), __expf(ALPHA * sljA));
                g_eli[base + 8 * H_] = make_float2(__expf(sliB), __expf(ALPHA * sliB));
                g_elj[base + 8 * H_] = make_float2(__expf(sljB), __expf(ALPHA * sljB));
            }
        }
    }

    // store F pre-rounded to tf32 (rna) so attn can cp.async it raw
#pragma unroll
    for (int mt = 0; mt < 2; mt++) {
        int row = m0 + wm + mt * 16 + g;
#pragma unroll
        for (int nt = 0; nt < 8; nt++) {
            int col = n0 + wn + nt * 8 + 2 * t;
            float2 v0 = make_float2(__uint_as_float(cvt_tf32(acc[mt][nt][0])),
                                    __uint_as_float(cvt_tf32(acc[mt][nt][1])));
            float2 v1 = make_float2(__uint_as_float(cvt_tf32(acc[mt][nt][2])),
                                    __uint_as_float(cvt_tf32(acc[mt][nt][3])));
            *(float2*)(out + (size_t)row * COUT + col) = v0;
            *(float2*)(out + (size_t)(row + 8) * COUT + col) = v1;
        }
    }
}

// ---------------------------------------------------------------------------
// Kernel 2: attention + aggregation via mma.sync tf32.
// Block: 64 i-rows of one batch, 256 threads = 8 warps = (mi 0..1) x (h 0..3).
// Warp tile 32i x 64c: each B fragment (F) LDS feeds TWO m-tiles -> B-fragment
// smem traffic halved vs 16-warp/16-row layout.
// ---------------------------------------------------------------------------
#define FSTR 264            // F smem row stride (floats)
#define FBUF (64 * FSTR)    // floats per buffer

__global__ __launch_bounds__(256, 1)
void attn_kernel(const int* __restrict__ adj, float* __restrict__ out)
{
    extern __shared__ float smem[];
    float*    Fs   = smem;                                // 2 buffers of 64*FSTR
    float2*   Elj  = (float2*)(Fs + 2 * FBUF);            // [1024][4]
    unsigned* bits = (unsigned*)(Elj + N_ * H_);          // [r][64][32]

    const uint32_t sF = (uint32_t)__cvta_generic_to_shared(Fs);

    const int tid = threadIdx.x;
    const int b  = blockIdx.x >> 4;                       // 128 blocks = 8 b x 16 tiles
    const int i0 = (blockIdx.x & 15) * 64;

    // ---- pack adjacency bits for all 4 relations (adj last dim is R) ----
    const int4* adj4 = (const int4*)adj;
    for (int tt = tid; tt < 64 * 32; tt += 256) {
        const int il = tt >> 5, jw = tt & 31;
        const int4* ap = adj4 + ((size_t)(b * N_ + i0 + il) * N_ + jw * 32);
        unsigned w0 = 0, w1 = 0, w2 = 0, w3 = 0;
#pragma unroll 8
        for (int jj = 0; jj < 32; jj++) {
            int4 v = ap[jj];
            w0 |= (unsigned)(v.x != 0) << jj;
            w1 |= (unsigned)(v.y != 0) << jj;
            w2 |= (unsigned)(v.z != 0) << jj;
            w3 |= (unsigned)(v.w != 0) << jj;
        }
        bits[(0 * 64 + il) * 32 + jw] = w0;
        bits[(1 * 64 + il) * 32 + jw] = w1;
        bits[(2 * 64 + il) * 32 + jw] = w2;
        bits[(3 * 64 + il) * 32 + jw] = w3;
    }

    const int warp = tid >> 5, lane = tid & 31;
    const int h = warp & 3, mi = warp >> 2;               // mi in {0,1}
    const int g = lane >> 2, t = lane & 3;
    const int base = mi * 32;
    const int r0 = base + g,  r1 = r0 + 8;                // m-tile 0 rows
    const int r2 = r0 + 16,   r3 = r0 + 24;               // m-tile 1 rows
    const int nb = h * 64;

    auto stageF = [&](const float* Fb, int jc) {
        const int buf = jc & 1;
        const float* src = Fb + (size_t)jc * 64 * COUT;
        const uint32_t dst = sF + (uint32_t)(buf * FBUF) * 4;
#pragma unroll
        for (int k = 0; k < 16; k++) {
            int e = k * 256 + tid;            // 0..4095 float4
            int row = e >> 6, c4 = e & 63;
            cpa16(dst + (uint32_t)(row * FSTR + c4 * 4) * 4, src + (size_t)e * 4);
        }
        CP_COMMIT();
    };

    float outacc[2][8][4];
#pragma unroll
    for (int mt = 0; mt < 2; mt++)
#pragma unroll
        for (int nt = 0; nt < 8; nt++)
#pragma unroll
            for (int k = 0; k < 4; k++) outacc[mt][nt][k] = 0.f;

    for (int r = 0; r < R_; r++) {
        {   // stage Elj for (r,b)
            const float4* src = (const float4*)(g_elj + (size_t)(r * B_ + b) * N_ * H_);
            float4* dst = (float4*)Elj;
#pragma unroll
            for (int k = 0; k < 8; k++) dst[k * 256 + tid] = src[k * 256 + tid];
        }
        const float* Fb = g_F + (size_t)(r * B_ + b) * N_ * COUT;
        stageF(Fb, 0);

        const size_t eib = ((size_t)(r * B_ + b) * N_ + i0) * H_ + h;
        const float2 ei0 = g_eli[eib + r0 * H_];
        const float2 ei1 = g_eli[eib + r1 * H_];
        const float2 ei2 = g_eli[eib + r2 * H_];
        const float2 ei3 = g_eli[eib + r3 * H_];

        float racc[2][8][4];
#pragma unroll
        for (int mt = 0; mt < 2; mt++)
#pragma unroll
            for (int nt = 0; nt < 8; nt++)
#pragma unroll
                for (int k = 0; k < 4; k++) racc[mt][nt][k] = 0.f;
        float es0 = 0.f, es1 = 0.f, es2 = 0.f, es3 = 0.f;

        const unsigned* bw0p = bits + (r * 64 + r0) * 32;
        const unsigned* bw1p = bits + (r * 64 + r1) * 32;
        const unsigned* bw2p = bits + (r * 64 + r2) * 32;
        const unsigned* bw3p = bits + (r * 64 + r3) * 32;

        for (int jc = 0; jc < 16; jc++) {
            if (jc + 1 < 16) { stageF(Fb, jc + 1); CP_WAIT(1); } else { CP_WAIT(0); }
            __syncthreads();
            const float* Fsb = Fs + (jc & 1) * FBUF;

            const unsigned bw0[2] = { bw0p[jc * 2], bw0p[jc * 2 + 1] };
            const unsigned bw1[2] = { bw1p[jc * 2], bw1p[jc * 2 + 1] };
            const unsigned bw2[2] = { bw2p[jc * 2], bw2p[jc * 2 + 1] };
            const unsigned bw3[2] = { bw3p[jc * 2], bw3p[jc * 2 + 1] };

#pragma unroll
            for (int kc = 0; kc < 8; kc++) {              // 8 k-slabs of 8 j's
                const int jb = kc * 8;
                const unsigned wr0 = bw0[kc >> 2], wr1 = bw1[kc >> 2];
                const unsigned wr2 = bw2[kc >> 2], wr3 = bw3[kc >> 2];
                const int sl = (jb & 31) + t;

                const float2 ejA = Elj[(jc * 64 + jb + t) * H_ + h];
                const float2 ejB = Elj[(jc * 64 + jb + t + 4) * H_ + h];

                // exp(leaky_relu(li+lj)) = max(e^li*e^lj, e^(a li)*e^(a lj))
                float e0A = fmaxf(ei0.x * ejA.x, ei0.y * ejA.y);
                float e1A = fmaxf(ei1.x * ejA.x, ei1.y * ejA.y);
                float e2A = fmaxf(ei2.x * ejA.x, ei2.y * ejA.y);
                float e3A = fmaxf(ei3.x * ejA.x, ei3.y * ejA.y);
                float e0B = fmaxf(ei0.x * ejB.x, ei0.y * ejB.y);
                float e1B = fmaxf(ei1.x * ejB.x, ei1.y * ejB.y);
                float e2B = fmaxf(ei2.x * ejB.x, ei2.y * ejB.y);
                float e3B = fmaxf(ei3.x * ejB.x, ei3.y * ejB.y);
                e0A = ((wr0 >> sl) & 1u)       ? e0A : 0.f;
                e1A = ((wr1 >> sl) & 1u)       ? e1A : 0.f;
                e2A = ((wr2 >> sl) & 1u)       ? e2A : 0.f;
                e3A = ((wr3 >> sl) & 1u)       ? e3A : 0.f;
                e0B = ((wr0 >> (sl + 4)) & 1u) ? e0B : 0.f;
                e1B = ((wr1 >> (sl + 4)) & 1u) ? e1B : 0.f;
                e2B = ((wr2 >> (sl + 4)) & 1u) ? e2B : 0.f;
                e3B = ((wr3 >> (sl + 4)) & 1u) ? e3B : 0.f;

                const unsigned a00 = cvt_tf32(e0A), a01 = cvt_tf32(e1A);
                const unsigned a02 = cvt_tf32(e0B), a03 = cvt_tf32(e1B);
                const unsigned a10 = cvt_tf32(e2A), a11 = cvt_tf32(e3A);
                const unsigned a12 = cvt_tf32(e2B), a13 = cvt_tf32(e3B);
                es0 += __uint_as_float(a00) + __uint_as_float(a02);
                es1 += __uint_as_float(a01) + __uint_as_float(a03);
                es2 += __uint_as_float(a10) + __uint_as_float(a12);
                es3 += __uint_as_float(a11) + __uint_as_float(a13);

                const float* brow0 = Fsb + (jb + t) * FSTR + nb + g;
                const float* brow1 = brow0 + 4 * FSTR;
#pragma unroll
                for (int nt = 0; nt < 8; nt++) {
                    unsigned b0 = __float_as_uint(brow0[nt * 8]);
                    unsigned b1 = __float_as_uint(brow1[nt * 8]);
                    mma_tf32(racc[0][nt], a00, a01, a02, a03, b0, b1);
                    mma_tf32(racc[1][nt], a10, a11, a12, a13, b0, b1);
                }
            }
            __syncthreads();                              // buffer free for restage
        }

        // row sums: reduce across the 4 lanes of each group
        es0 += __shfl_xor_sync(0xffffffffu, es0, 1);
        es0 += __shfl_xor_sync(0xffffffffu, es0, 2);
        es1 += __shfl_xor_sync(0xffffffffu, es1, 1);
        es1 += __shfl_xor_sync(0xffffffffu, es1, 2);
        es2 += __shfl_xor_sync(0xffffffffu, es2, 1);
        es2 += __shfl_xor_sync(0xffffffffu, es2, 2);
        es3 += __shfl_xor_sync(0xffffffffu, es3, 1);
        es3 += __shfl_xor_sync(0xffffffffu, es3, 2);
        const float inv0 = es0 > 0.f ? 1.0f / es0 : 0.f;
        const float inv1 = es1 > 0.f ? 1.0f / es1 : 0.f;
        const float inv2 = es2 > 0.f ? 1.0f / es2 : 0.f;
        const float inv3 = es3 > 0.f ? 1.0f / es3 : 0.f;

#pragma unroll
        for (int nt = 0; nt < 8; nt++) {
            outacc[0][nt][0] += racc[0][nt][0] * inv0;
            outacc[0][nt][1] += racc[0][nt][1] * inv0;
            outacc[0][nt][2] += racc[0][nt][2] * inv1;
            outacc[0][nt][3] += racc[0][nt][3] * inv1;
            outacc[1][nt][0] += racc[1][nt][0] * inv2;
            outacc[1][nt][1] += racc[1][nt][1] * inv2;
            outacc[1][nt][2] += racc[1][nt][2] * inv3;
            outacc[1][nt][3] += racc[1][nt][3] * inv3;
        }
        __syncthreads();                                  // Elj free for next r
    }

    // store: out[b, i, h*64 + c]
    float* o0 = out + ((size_t)b * N_ + i0 + r0) * COUT + nb + 2 * t;
    float* o1 = out + ((size_t)b * N_ + i0 + r1) * COUT + nb + 2 * t;
    float* o2 = out + ((size_t)b * N_ + i0 + r2) * COUT + nb + 2 * t;
    float* o3 = out + ((size_t)b * N_ + i0 + r3) * COUT + nb + 2 * t;
#pragma unroll
    for (int nt = 0; nt < 8; nt++) {
        *(float2*)(o0 + nt * 8) = make_float2(outacc[0][nt][0], outacc[0][nt][1]);
        *(float2*)(o1 + nt * 8) = make_float2(outacc[0][nt][2], outacc[0][nt][3]);
        *(float2*)(o2 + nt * 8) = make_float2(outacc[1][nt][0], outacc[1][nt][1]);
        *(float2*)(o3 + nt * 8) = make_float2(outacc[1][nt][2], outacc[1][nt][3]);
    }
}

// ---------------------------------------------------------------------------
extern "C" void kernel_launch(void* const* d_in, const int* in_sizes, int n_in,
                              void* d_out, int out_size)
{
    const float* X   = (const float*)d_in[0];   // node_feats (B,N,CIN)
    const int*   adj = (const int*)  d_in[1];   // adj (B,N,N,R)
    const float* W   = (const float*)d_in[2];   // (R,CIN,COUT)
    const float* a   = (const float*)d_in[3];   // (R,H,2C)
    float* out = (float*)d_out;                 // (B,N,H*C)

    gemm_kernel<<<dim3(N_ / 128, COUT / 128, R_ * B_), 256>>>(X, W, a);

    const int SMEM = (2 * FBUF) * 4 + (N_ * H_) * 8 + (R_ * 64 * 32) * 4;  // 200704 B
    cudaFuncSetAttribute(attn_kernel, cudaFuncAttributeMaxDynamicSharedMemorySize, SMEM);
    attn_kernel<<<(B_ * N_) / 64, 256, SMEM>>>(adj, out);
}